// round 2
// baseline (speedup 1.0000x reference)
#include <cuda_runtime.h>
#include <math.h>

#define NEXP   4096
#define NPTS   65536
#define NRAYS  1024
#define HID    32
#define IN_PTS 63
#define IN_DIR 27
#define IN_VIEW 59

// ---- scratch (no allocations allowed) ----
__device__ int g_counts[NEXP];
__device__ int g_offsets[NEXP];
__device__ int g_cursor[NEXP];
__device__ int g_expert[NPTS];
__device__ int g_sorted[NPTS];

// ---------------------------------------------------------------- zero
__global__ void k_zero_counts() {
    int i = blockIdx.x * blockDim.x + threadIdx.x;
    if (i < NEXP) g_counts[i] = 0;
}

// ---------------------------------------------------------------- classify
__global__ void k_classify(const float* __restrict__ pts) {
    int n = blockIdx.x * blockDim.x + threadIdx.x;
    if (n >= NPTS) return;
    float x = pts[n * 3 + 0];
    float y = pts[n * 3 + 1];
    float z = pts[n * 3 + 2];
    // norm = (p - AABB_MIN) / (AABB_MAX - AABB_MIN); scaled = clip(norm*R, 0, R-1)
    float sx = fminf(fmaxf(((x + 1.5f) / 3.0f) * 16.0f, 0.0f), 15.0f);
    float sy = fminf(fmaxf(((y + 1.5f) / 3.0f) * 16.0f, 0.0f), 15.0f);
    float sz = fminf(fmaxf(((z + 1.5f) / 3.0f) * 16.0f, 0.0f), 15.0f);
    int e = ((int)sx) * 256 + ((int)sy) * 16 + (int)sz;
    g_expert[n] = e;
    atomicAdd(&g_counts[e], 1);
}

// ---------------------------------------------------------------- scan (1 block, 1024 thr, 4 per thr)
__global__ void k_scan() {
    __shared__ int wsum[32];
    int tid  = threadIdx.x;
    int base = tid * 4;
    int c0 = g_counts[base + 0];
    int c1 = g_counts[base + 1];
    int c2 = g_counts[base + 2];
    int c3 = g_counts[base + 3];
    int local = c0 + c1 + c2 + c3;
    int lane = tid & 31, w = tid >> 5;
    int v = local;
    #pragma unroll
    for (int off = 1; off < 32; off <<= 1) {
        int t = __shfl_up_sync(0xFFFFFFFFu, v, off);
        if (lane >= off) v += t;
    }
    if (lane == 31) wsum[w] = v;
    __syncthreads();
    if (w == 0) {
        int s = wsum[lane];
        #pragma unroll
        for (int off = 1; off < 32; off <<= 1) {
            int t = __shfl_up_sync(0xFFFFFFFFu, s, off);
            if (lane >= off) s += t;
        }
        wsum[lane] = s;
    }
    __syncthreads();
    int prefix = v - local;              // exclusive within warp
    if (w > 0) prefix += wsum[w - 1];
    int run = prefix;
    g_offsets[base + 0] = run; g_cursor[base + 0] = run; run += c0;
    g_offsets[base + 1] = run; g_cursor[base + 1] = run; run += c1;
    g_offsets[base + 2] = run; g_cursor[base + 2] = run; run += c2;
    g_offsets[base + 3] = run; g_cursor[base + 3] = run; run += c3;
}

// ---------------------------------------------------------------- scatter
__global__ void k_scatter() {
    int n = blockIdx.x * blockDim.x + threadIdx.x;
    if (n >= NPTS) return;
    int e = g_expert[n];
    int pos = atomicAdd(&g_cursor[e], 1);
    g_sorted[pos] = n;
}

// ---------------------------------------------------------------- main MLP: 1 block per expert
__global__ __launch_bounds__(128) void k_mlp(
    const float* __restrict__ pts, const float* __restrict__ dirs,
    const float* __restrict__ W1, const float* __restrict__ b1,
    const float* __restrict__ W2, const float* __restrict__ b2,
    const float* __restrict__ Wf, const float* __restrict__ bf,
    const float* __restrict__ Wsig, const float* __restrict__ bsig,
    const float* __restrict__ Wv, const float* __restrict__ bv,
    const float* __restrict__ Wrgb, const float* __restrict__ brgb,
    float* __restrict__ out_rgb, float* __restrict__ out_sig)
{
    int e = blockIdx.x;
    int count = g_counts[e];
    if (count == 0) return;
    int start = g_offsets[e];

    __shared__ float sW1[IN_PTS * HID];     // 2016
    __shared__ float sW2[HID * HID];        // 1024
    __shared__ float sWf[HID * HID];        // 1024
    __shared__ float sWv[IN_VIEW * HID];    // 1888
    __shared__ float sWsig[HID];
    __shared__ float sWrgb[HID * 3];
    __shared__ float sb1[HID], sb2[HID], sbf[HID], sbv[HID];
    __shared__ float sbrgb[3], sbsig[1];
    __shared__ float sAct[4][128];          // per warp: xp[0..62], xd @64..90, h @96..127

    int tid = threadIdx.x;
    // cooperative weight load
    {
        const float* p1 = W1 + (size_t)e * IN_PTS * HID;
        for (int i = tid; i < IN_PTS * HID; i += 128) sW1[i] = p1[i];
        const float* p2 = W2 + (size_t)e * HID * HID;
        for (int i = tid; i < HID * HID; i += 128) sW2[i] = p2[i];
        const float* pf = Wf + (size_t)e * HID * HID;
        for (int i = tid; i < HID * HID; i += 128) sWf[i] = pf[i];
        const float* pv = Wv + (size_t)e * IN_VIEW * HID;
        for (int i = tid; i < IN_VIEW * HID; i += 128) sWv[i] = pv[i];
        if (tid < HID) {
            sWsig[tid] = Wsig[(size_t)e * HID + tid];
            sb1[tid] = b1[(size_t)e * HID + tid];
            sb2[tid] = b2[(size_t)e * HID + tid];
            sbf[tid] = bf[(size_t)e * HID + tid];
            sbv[tid] = bv[(size_t)e * HID + tid];
        }
        if (tid >= 32 && tid < 32 + HID * 3) sWrgb[tid - 32] = Wrgb[(size_t)e * HID * 3 + (tid - 32)];
        if (tid == 0) sbsig[0] = bsig[e];
        if (tid >= 128 - 3) sbrgb[tid - 125] = brgb[(size_t)e * 3 + (tid - 125)];
    }
    __syncthreads();

    int w = tid >> 5, lane = tid & 31;
    float* xp = sAct[w];
    float* xd = xp + 64;
    float* hb = xp + 96;

    for (int k = w; k < count; k += 4) {
        int n = g_sorted[start + k];
        const float* pp = pts + (size_t)n * 3;
        float px = pp[0], py = pp[1], pz = pp[2];
        const float* dd = dirs + (size_t)(n >> 6) * 3;
        float dx = dd[0], dy = dd[1], dz = dd[2];

        // positional encoding, distributed over lanes
        if (lane < 3) xp[lane] = (lane == 0) ? px : ((lane == 1) ? py : pz);
        if (lane < 30) {
            int f = lane / 3, a = lane - f * 3;
            float base = (a == 0) ? px : ((a == 1) ? py : pz);
            float arg = base * (float)(1 << f);      // exact (power-of-two mult)
            float s, c;
            sincosf(arg, &s, &c);
            xp[3 + 6 * f + a] = s;
            xp[6 + 6 * f + a] = c;
        }
        if (lane < 3) xd[lane] = (lane == 0) ? dx : ((lane == 1) ? dy : dz);
        if (lane < 12) {
            int f = lane / 3, a = lane - f * 3;
            float base = (a == 0) ? dx : ((a == 1) ? dy : dz);
            float arg = base * (float)(1 << f);
            float s, c;
            sincosf(arg, &s, &c);
            xd[3 + 6 * f + a] = s;
            xd[6 + 6 * f + a] = c;
        }
        __syncwarp();

        // layer 1: 63 -> 32, relu
        float h = sb1[lane];
        #pragma unroll
        for (int i = 0; i < IN_PTS; i++) h = fmaf(xp[i], sW1[i * HID + lane], h);
        h = fmaxf(h, 0.0f);
        hb[lane] = h;
        __syncwarp();

        // layer 2: 32 -> 32, relu
        float h2 = sb2[lane];
        #pragma unroll
        for (int i = 0; i < HID; i++) h2 = fmaf(hb[i], sW2[i * HID + lane], h2);
        h2 = fmaxf(h2, 0.0f);

        // sigma (linear): reduce h2 * Wsig over lanes
        float sg = h2 * sWsig[lane];
        #pragma unroll
        for (int o = 16; o > 0; o >>= 1) sg += __shfl_xor_sync(0xFFFFFFFFu, sg, o);

        __syncwarp();
        hb[lane] = h2;
        __syncwarp();

        // feature (linear): 32 -> 32
        float ft = sbf[lane];
        #pragma unroll
        for (int i = 0; i < HID; i++) ft = fmaf(hb[i], sWf[i * HID + lane], ft);

        __syncwarp();
        hb[lane] = ft;
        __syncwarp();

        // view layer: [feat(32), xd(27)] -> 32, relu
        float vv = sbv[lane];
        #pragma unroll
        for (int i = 0; i < HID; i++) vv = fmaf(hb[i], sWv[i * HID + lane], vv);
        #pragma unroll
        for (int j = 0; j < IN_DIR; j++) vv = fmaf(xd[j], sWv[(HID + j) * HID + lane], vv);
        vv = fmaxf(vv, 0.0f);

        // rgb (linear): 32 -> 3, via per-lane partials + reduce
        float r0 = vv * sWrgb[lane * 3 + 0];
        float r1 = vv * sWrgb[lane * 3 + 1];
        float r2 = vv * sWrgb[lane * 3 + 2];
        #pragma unroll
        for (int o = 16; o > 0; o >>= 1) {
            r0 += __shfl_xor_sync(0xFFFFFFFFu, r0, o);
            r1 += __shfl_xor_sync(0xFFFFFFFFu, r1, o);
            r2 += __shfl_xor_sync(0xFFFFFFFFu, r2, o);
        }

        if (lane == 0) {
            out_sig[n] = sg + sbsig[0];
            out_rgb[(size_t)n * 3 + 0] = r0 + sbrgb[0];
            out_rgb[(size_t)n * 3 + 1] = r1 + sbrgb[1];
            out_rgb[(size_t)n * 3 + 2] = r2 + sbrgb[2];
        }
        __syncwarp();   // protect xp/xd/hb before next iteration's writes
    }
}

// ---------------------------------------------------------------- launch
extern "C" void kernel_launch(void* const* d_in, const int* in_sizes, int n_in,
                              void* d_out, int out_size) {
    const float* pts  = (const float*)d_in[0];
    const float* dirs = (const float*)d_in[1];
    const float* W1   = (const float*)d_in[2];
    const float* b1   = (const float*)d_in[3];
    const float* W2   = (const float*)d_in[4];
    const float* b2   = (const float*)d_in[5];
    const float* Wf   = (const float*)d_in[6];
    const float* bf   = (const float*)d_in[7];
    const float* Wsig = (const float*)d_in[8];
    const float* bsig = (const float*)d_in[9];
    const float* Wv   = (const float*)d_in[10];
    const float* bv   = (const float*)d_in[11];
    const float* Wrgb = (const float*)d_in[12];
    const float* brgb = (const float*)d_in[13];

    float* out_rgb = (float*)d_out;
    float* out_sig = (float*)d_out + (size_t)NPTS * 3;

    k_zero_counts<<<NEXP / 256, 256>>>();
    k_classify<<<NPTS / 256, 256>>>(pts);
    k_scan<<<1, 1024>>>();
    k_scatter<<<NPTS / 256, 256>>>();
    k_mlp<<<NEXP, 128>>>(pts, dirs, W1, b1, W2, b2, Wf, bf, Wsig, bsig,
                         Wv, bv, Wrgb, brgb, out_rgb, out_sig);
}

// round 3
// speedup vs baseline: 1.4441x; 1.4441x over previous
#include <cuda_runtime.h>
#include <math.h>

#define NEXP   4096
#define NPTS   65536
#define NRAYS  1024
#define HID    32
#define IN_PTS 63
#define IN_DIR 27
#define IN_VIEW 59

// ---- scratch (no allocations allowed) ----
__device__ int    g_counts[NEXP];
__device__ int    g_offsets[NEXP];
__device__ int    g_expert[NPTS];
__device__ int    g_rank[NPTS];
__device__ int    g_sorted[NPTS];
__device__ float4 g_xp4[NPTS * 16];   // per-point xyz PE, 63 floats padded to 64
__device__ float4 g_xd4[NRAYS * 8];   // per-ray dir PE, 27 floats padded to 32

// ---------------------------------------------------------------- init: zero counts + dir PE
__global__ void k_init(const float* __restrict__ dirs) {
    int t = blockIdx.x * blockDim.x + threadIdx.x;   // 4096 threads
    g_counts[t] = 0;
    if (t < NRAYS) {
        float x = dirs[t * 3 + 0];
        float y = dirs[t * 3 + 1];
        float z = dirs[t * 3 + 2];
        float row[32];
        row[0] = x; row[1] = y; row[2] = z;
        #pragma unroll
        for (int f = 0; f < 4; f++) {
            float m = (float)(1 << f);
            float s, c;
            sincosf(x * m, &s, &c); row[3 + 6 * f + 0] = s; row[6 + 6 * f + 0] = c;
            sincosf(y * m, &s, &c); row[3 + 6 * f + 1] = s; row[6 + 6 * f + 1] = c;
            sincosf(z * m, &s, &c); row[3 + 6 * f + 2] = s; row[6 + 6 * f + 2] = c;
        }
        row[27] = 0.f; row[28] = 0.f; row[29] = 0.f; row[30] = 0.f; row[31] = 0.f;
        float4* d = &g_xd4[t * 8];
        #pragma unroll
        for (int q = 0; q < 8; q++)
            d[q] = make_float4(row[4 * q], row[4 * q + 1], row[4 * q + 2], row[4 * q + 3]);
    }
}

// ---------------------------------------------------------------- classify + xyz PE + rank
__global__ void k_prep(const float* __restrict__ pts) {
    int n = blockIdx.x * blockDim.x + threadIdx.x;   // 65536 threads
    float x = pts[n * 3 + 0];
    float y = pts[n * 3 + 1];
    float z = pts[n * 3 + 2];

    float sx = fminf(fmaxf(((x + 1.5f) / 3.0f) * 16.0f, 0.0f), 15.0f);
    float sy = fminf(fmaxf(((y + 1.5f) / 3.0f) * 16.0f, 0.0f), 15.0f);
    float sz = fminf(fmaxf(((z + 1.5f) / 3.0f) * 16.0f, 0.0f), 15.0f);
    int e = ((int)sx) * 256 + ((int)sy) * 16 + (int)sz;
    g_expert[n] = e;
    g_rank[n] = atomicAdd(&g_counts[e], 1);

    float row[64];
    row[0] = x; row[1] = y; row[2] = z;
    #pragma unroll
    for (int f = 0; f < 10; f++) {
        float m = (float)(1 << f);
        float s, c;
        sincosf(x * m, &s, &c); row[3 + 6 * f + 0] = s; row[6 + 6 * f + 0] = c;
        sincosf(y * m, &s, &c); row[3 + 6 * f + 1] = s; row[6 + 6 * f + 1] = c;
        sincosf(z * m, &s, &c); row[3 + 6 * f + 2] = s; row[6 + 6 * f + 2] = c;
    }
    row[63] = 0.f;
    float4* d = &g_xp4[n * 16];
    #pragma unroll
    for (int q = 0; q < 16; q++)
        d[q] = make_float4(row[4 * q], row[4 * q + 1], row[4 * q + 2], row[4 * q + 3]);
}

// ---------------------------------------------------------------- scan (1 block, 1024 thr, 4 per thr)
__global__ void k_scan() {
    __shared__ int wsum[32];
    int tid  = threadIdx.x;
    int base = tid * 4;
    int c0 = g_counts[base + 0];
    int c1 = g_counts[base + 1];
    int c2 = g_counts[base + 2];
    int c3 = g_counts[base + 3];
    int local = c0 + c1 + c2 + c3;
    int lane = tid & 31, w = tid >> 5;
    int v = local;
    #pragma unroll
    for (int off = 1; off < 32; off <<= 1) {
        int t = __shfl_up_sync(0xFFFFFFFFu, v, off);
        if (lane >= off) v += t;
    }
    if (lane == 31) wsum[w] = v;
    __syncthreads();
    if (w == 0) {
        int s = wsum[lane];
        #pragma unroll
        for (int off = 1; off < 32; off <<= 1) {
            int t = __shfl_up_sync(0xFFFFFFFFu, s, off);
            if (lane >= off) s += t;
        }
        wsum[lane] = s;
    }
    __syncthreads();
    int prefix = v - local;
    if (w > 0) prefix += wsum[w - 1];
    int run = prefix;
    g_offsets[base + 0] = run; run += c0;
    g_offsets[base + 1] = run; run += c1;
    g_offsets[base + 2] = run; run += c2;
    g_offsets[base + 3] = run;
}

// ---------------------------------------------------------------- scatter (atomic-free)
__global__ void k_scatter() {
    int n = blockIdx.x * blockDim.x + threadIdx.x;
    int e = g_expert[n];
    g_sorted[g_offsets[e] + g_rank[n]] = n;
}

// ---------------------------------------------------------------- main MLP: 1 block per expert, 4 pts/warp
__global__ __launch_bounds__(128) void k_mlp(
    const float* __restrict__ W1, const float* __restrict__ b1,
    const float* __restrict__ W2, const float* __restrict__ b2,
    const float* __restrict__ Wf, const float* __restrict__ bf,
    const float* __restrict__ Wsig, const float* __restrict__ bsig,
    const float* __restrict__ Wv, const float* __restrict__ bv,
    const float* __restrict__ Wrgb, const float* __restrict__ brgb,
    float* __restrict__ out_rgb, float* __restrict__ out_sig)
{
    int e = blockIdx.x;
    int count = g_counts[e];
    if (count == 0) return;
    int start = g_offsets[e];

    __shared__ __align__(16) float sW1[IN_PTS * HID];     // 2016
    __shared__ __align__(16) float sW2[HID * HID];        // 1024
    __shared__ __align__(16) float sWf[HID * HID];        // 1024
    __shared__ __align__(16) float sWv[IN_VIEW * HID];    // 1888
    __shared__ float sWsig[HID];
    __shared__ float sWrgb[HID * 3];
    __shared__ float sb1[HID], sb2[HID], sbf[HID], sbv[HID];
    __shared__ float sconst[4];                           // bsig, brgb[0..2]
    __shared__ __align__(16) float sxp[4][4 * 64];
    __shared__ __align__(16) float sxd[4][4 * 32];
    __shared__ __align__(16) float sh [4][4 * 32];

    int tid = threadIdx.x;
    {
        const float4* s1 = (const float4*)(W1 + (size_t)e * IN_PTS * HID);
        float4* d1 = (float4*)sW1;
        for (int i = tid; i < IN_PTS * HID / 4; i += 128) d1[i] = s1[i];
        const float4* s2 = (const float4*)(W2 + (size_t)e * HID * HID);
        float4* d2 = (float4*)sW2;
        for (int i = tid; i < HID * HID / 4; i += 128) d2[i] = s2[i];
        const float4* sf = (const float4*)(Wf + (size_t)e * HID * HID);
        float4* df = (float4*)sWf;
        for (int i = tid; i < HID * HID / 4; i += 128) df[i] = sf[i];
        const float4* sv = (const float4*)(Wv + (size_t)e * IN_VIEW * HID);
        float4* dv = (float4*)sWv;
        for (int i = tid; i < IN_VIEW * HID / 4; i += 128) dv[i] = sv[i];
        if (tid < HID) {
            sWsig[tid] = Wsig[(size_t)e * HID + tid];
            sb1[tid] = b1[(size_t)e * HID + tid];
            sb2[tid] = b2[(size_t)e * HID + tid];
            sbf[tid] = bf[(size_t)e * HID + tid];
            sbv[tid] = bv[(size_t)e * HID + tid];
        }
        if (tid >= 32 && tid < 128) sWrgb[tid - 32] = Wrgb[(size_t)e * HID * 3 + (tid - 32)];
        if (tid < 4) sconst[tid] = (tid == 0) ? bsig[e] : brgb[(size_t)e * 3 + tid - 1];
    }
    __syncthreads();

    int w = tid >> 5, lane = tid & 31;
    float* xpw = sxp[w];
    float* xdw = sxd[w];
    float* shw = sh[w];

    // hoisted per-lane constants
    float bb1 = sb1[lane], bb2 = sb2[lane], bbf = sbf[lane], bbv = sbv[lane];
    float wsg = sWsig[lane];
    float wr0 = sWrgb[lane * 3 + 0], wr1 = sWrgb[lane * 3 + 1], wr2 = sWrgb[lane * 3 + 2];
    float bsg = sconst[0], br0 = sconst[1], br1 = sconst[2], br2 = sconst[3];

    for (int kb = w * 4; kb < count; kb += 16) {
        int n0 = g_sorted[start + min(kb + 0, count - 1)];
        int n1 = g_sorted[start + min(kb + 1, count - 1)];
        int n2 = g_sorted[start + min(kb + 2, count - 1)];
        int n3 = g_sorted[start + min(kb + 3, count - 1)];

        // xp: 64 quads (4 pts x 16), 2 per lane
        {
            int hp = lane >> 4, q = lane & 15;
            int na = (hp == 0) ? n0 : n1;
            int nb = (hp == 0) ? n2 : n3;
            ((float4*)xpw)[lane]      = g_xp4[(size_t)na * 16 + q];
            ((float4*)xpw)[lane + 32] = g_xp4[(size_t)nb * 16 + q];
        }
        // xd: 32 quads (4 pts x 8), 1 per lane
        {
            int p = lane >> 3, q = lane & 7;
            int nn = (p == 0) ? n0 : (p == 1) ? n1 : (p == 2) ? n2 : n3;
            ((float4*)xdw)[lane] = g_xd4[(size_t)(nn >> 6) * 8 + q];
        }
        __syncwarp();

        // ---- layer 1: 63 -> 32, relu ----
        float h0 = bb1, h1 = bb1, h2 = bb1, h3 = bb1;
        #pragma unroll
        for (int i = 0; i < 60; i += 4) {
            float wa = sW1[(i + 0) * 32 + lane];
            float wb = sW1[(i + 1) * 32 + lane];
            float wc = sW1[(i + 2) * 32 + lane];
            float wd = sW1[(i + 3) * 32 + lane];
            float4 x0 = *(const float4*)&xpw[0 * 64 + i];
            float4 x1 = *(const float4*)&xpw[1 * 64 + i];
            float4 x2 = *(const float4*)&xpw[2 * 64 + i];
            float4 x3 = *(const float4*)&xpw[3 * 64 + i];
            h0 = fmaf(x0.x, wa, h0); h0 = fmaf(x0.y, wb, h0); h0 = fmaf(x0.z, wc, h0); h0 = fmaf(x0.w, wd, h0);
            h1 = fmaf(x1.x, wa, h1); h1 = fmaf(x1.y, wb, h1); h1 = fmaf(x1.z, wc, h1); h1 = fmaf(x1.w, wd, h1);
            h2 = fmaf(x2.x, wa, h2); h2 = fmaf(x2.y, wb, h2); h2 = fmaf(x2.z, wc, h2); h2 = fmaf(x2.w, wd, h2);
            h3 = fmaf(x3.x, wa, h3); h3 = fmaf(x3.y, wb, h3); h3 = fmaf(x3.z, wc, h3); h3 = fmaf(x3.w, wd, h3);
        }
        #pragma unroll
        for (int i = 60; i < 63; i++) {
            float wa = sW1[i * 32 + lane];
            h0 = fmaf(xpw[0 * 64 + i], wa, h0);
            h1 = fmaf(xpw[1 * 64 + i], wa, h1);
            h2 = fmaf(xpw[2 * 64 + i], wa, h2);
            h3 = fmaf(xpw[3 * 64 + i], wa, h3);
        }
        h0 = fmaxf(h0, 0.f); h1 = fmaxf(h1, 0.f); h2 = fmaxf(h2, 0.f); h3 = fmaxf(h3, 0.f);
        shw[0 * 32 + lane] = h0; shw[1 * 32 + lane] = h1;
        shw[2 * 32 + lane] = h2; shw[3 * 32 + lane] = h3;
        __syncwarp();

        // ---- layer 2: 32 -> 32, relu ----
        float g0 = bb2, g1 = bb2, g2 = bb2, g3 = bb2;
        #pragma unroll
        for (int i = 0; i < 32; i += 4) {
            float wa = sW2[(i + 0) * 32 + lane];
            float wb = sW2[(i + 1) * 32 + lane];
            float wc = sW2[(i + 2) * 32 + lane];
            float wd = sW2[(i + 3) * 32 + lane];
            float4 x0 = *(const float4*)&shw[0 * 32 + i];
            float4 x1 = *(const float4*)&shw[1 * 32 + i];
            float4 x2 = *(const float4*)&shw[2 * 32 + i];
            float4 x3 = *(const float4*)&shw[3 * 32 + i];
            g0 = fmaf(x0.x, wa, g0); g0 = fmaf(x0.y, wb, g0); g0 = fmaf(x0.z, wc, g0); g0 = fmaf(x0.w, wd, g0);
            g1 = fmaf(x1.x, wa, g1); g1 = fmaf(x1.y, wb, g1); g1 = fmaf(x1.z, wc, g1); g1 = fmaf(x1.w, wd, g1);
            g2 = fmaf(x2.x, wa, g2); g2 = fmaf(x2.y, wb, g2); g2 = fmaf(x2.z, wc, g2); g2 = fmaf(x2.w, wd, g2);
            g3 = fmaf(x3.x, wa, g3); g3 = fmaf(x3.y, wb, g3); g3 = fmaf(x3.z, wc, g3); g3 = fmaf(x3.w, wd, g3);
        }
        g0 = fmaxf(g0, 0.f); g1 = fmaxf(g1, 0.f); g2 = fmaxf(g2, 0.f); g3 = fmaxf(g3, 0.f);

        // sigma partials
        float s0 = g0 * wsg, s1 = g1 * wsg, s2 = g2 * wsg, s3 = g3 * wsg;

        __syncwarp();
        shw[0 * 32 + lane] = g0; shw[1 * 32 + lane] = g1;
        shw[2 * 32 + lane] = g2; shw[3 * 32 + lane] = g3;
        __syncwarp();

        // ---- feature: 32 -> 32 (linear) ----
        float f0 = bbf, f1 = bbf, f2 = bbf, f3 = bbf;
        #pragma unroll
        for (int i = 0; i < 32; i += 4) {
            float wa = sWf[(i + 0) * 32 + lane];
            float wb = sWf[(i + 1) * 32 + lane];
            float wc = sWf[(i + 2) * 32 + lane];
            float wd = sWf[(i + 3) * 32 + lane];
            float4 x0 = *(const float4*)&shw[0 * 32 + i];
            float4 x1 = *(const float4*)&shw[1 * 32 + i];
            float4 x2 = *(const float4*)&shw[2 * 32 + i];
            float4 x3 = *(const float4*)&shw[3 * 32 + i];
            f0 = fmaf(x0.x, wa, f0); f0 = fmaf(x0.y, wb, f0); f0 = fmaf(x0.z, wc, f0); f0 = fmaf(x0.w, wd, f0);
            f1 = fmaf(x1.x, wa, f1); f1 = fmaf(x1.y, wb, f1); f1 = fmaf(x1.z, wc, f1); f1 = fmaf(x1.w, wd, f1);
            f2 = fmaf(x2.x, wa, f2); f2 = fmaf(x2.y, wb, f2); f2 = fmaf(x2.z, wc, f2); f2 = fmaf(x2.w, wd, f2);
            f3 = fmaf(x3.x, wa, f3); f3 = fmaf(x3.y, wb, f3); f3 = fmaf(x3.z, wc, f3); f3 = fmaf(x3.w, wd, f3);
        }
        __syncwarp();
        shw[0 * 32 + lane] = f0; shw[1 * 32 + lane] = f1;
        shw[2 * 32 + lane] = f2; shw[3 * 32 + lane] = f3;
        __syncwarp();

        // ---- view layer: [feat(32), xd(27)] -> 32, relu ----
        float v0 = bbv, v1 = bbv, v2 = bbv, v3 = bbv;
        #pragma unroll
        for (int i = 0; i < 32; i += 4) {
            float wa = sWv[(i + 0) * 32 + lane];
            float wb = sWv[(i + 1) * 32 + lane];
            float wc = sWv[(i + 2) * 32 + lane];
            float wd = sWv[(i + 3) * 32 + lane];
            float4 x0 = *(const float4*)&shw[0 * 32 + i];
            float4 x1 = *(const float4*)&shw[1 * 32 + i];
            float4 x2 = *(const float4*)&shw[2 * 32 + i];
            float4 x3 = *(const float4*)&shw[3 * 32 + i];
            v0 = fmaf(x0.x, wa, v0); v0 = fmaf(x0.y, wb, v0); v0 = fmaf(x0.z, wc, v0); v0 = fmaf(x0.w, wd, v0);
            v1 = fmaf(x1.x, wa, v1); v1 = fmaf(x1.y, wb, v1); v1 = fmaf(x1.z, wc, v1); v1 = fmaf(x1.w, wd, v1);
            v2 = fmaf(x2.x, wa, v2); v2 = fmaf(x2.y, wb, v2); v2 = fmaf(x2.z, wc, v2); v2 = fmaf(x2.w, wd, v2);
            v3 = fmaf(x3.x, wa, v3); v3 = fmaf(x3.y, wb, v3); v3 = fmaf(x3.z, wc, v3); v3 = fmaf(x3.w, wd, v3);
        }
        #pragma unroll
        for (int j = 0; j < 24; j += 4) {
            float wa = sWv[(HID + j + 0) * 32 + lane];
            float wb = sWv[(HID + j + 1) * 32 + lane];
            float wc = sWv[(HID + j + 2) * 32 + lane];
            float wd = sWv[(HID + j + 3) * 32 + lane];
            float4 x0 = *(const float4*)&xdw[0 * 32 + j];
            float4 x1 = *(const float4*)&xdw[1 * 32 + j];
            float4 x2 = *(const float4*)&xdw[2 * 32 + j];
            float4 x3 = *(const float4*)&xdw[3 * 32 + j];
            v0 = fmaf(x0.x, wa, v0); v0 = fmaf(x0.y, wb, v0); v0 = fmaf(x0.z, wc, v0); v0 = fmaf(x0.w, wd, v0);
            v1 = fmaf(x1.x, wa, v1); v1 = fmaf(x1.y, wb, v1); v1 = fmaf(x1.z, wc, v1); v1 = fmaf(x1.w, wd, v1);
            v2 = fmaf(x2.x, wa, v2); v2 = fmaf(x2.y, wb, v2); v2 = fmaf(x2.z, wc, v2); v2 = fmaf(x2.w, wd, v2);
            v3 = fmaf(x3.x, wa, v3); v3 = fmaf(x3.y, wb, v3); v3 = fmaf(x3.z, wc, v3); v3 = fmaf(x3.w, wd, v3);
        }
        #pragma unroll
        for (int j = 24; j < IN_DIR; j++) {
            float wa = sWv[(HID + j) * 32 + lane];
            v0 = fmaf(xdw[0 * 32 + j], wa, v0);
            v1 = fmaf(xdw[1 * 32 + j], wa, v1);
            v2 = fmaf(xdw[2 * 32 + j], wa, v2);
            v3 = fmaf(xdw[3 * 32 + j], wa, v3);
        }
        v0 = fmaxf(v0, 0.f); v1 = fmaxf(v1, 0.f); v2 = fmaxf(v2, 0.f); v3 = fmaxf(v3, 0.f);

        // rgb partials: r[p][c]
        float r0x = v0 * wr0, r0y = v0 * wr1, r0z = v0 * wr2;
        float r1x = v1 * wr0, r1y = v1 * wr1, r1z = v1 * wr2;
        float r2x = v2 * wr0, r2y = v2 * wr1, r2z = v2 * wr2;
        float r3x = v3 * wr0, r3y = v3 * wr1, r3z = v3 * wr2;

        // butterfly reductions (16 values)
        #pragma unroll
        for (int o = 16; o > 0; o >>= 1) {
            s0  += __shfl_xor_sync(0xFFFFFFFFu, s0,  o);
            s1  += __shfl_xor_sync(0xFFFFFFFFu, s1,  o);
            s2  += __shfl_xor_sync(0xFFFFFFFFu, s2,  o);
            s3  += __shfl_xor_sync(0xFFFFFFFFu, s3,  o);
            r0x += __shfl_xor_sync(0xFFFFFFFFu, r0x, o);
            r0y += __shfl_xor_sync(0xFFFFFFFFu, r0y, o);
            r0z += __shfl_xor_sync(0xFFFFFFFFu, r0z, o);
            r1x += __shfl_xor_sync(0xFFFFFFFFu, r1x, o);
            r1y += __shfl_xor_sync(0xFFFFFFFFu, r1y, o);
            r1z += __shfl_xor_sync(0xFFFFFFFFu, r1z, o);
            r2x += __shfl_xor_sync(0xFFFFFFFFu, r2x, o);
            r2y += __shfl_xor_sync(0xFFFFFFFFu, r2y, o);
            r2z += __shfl_xor_sync(0xFFFFFFFFu, r2z, o);
            r3x += __shfl_xor_sync(0xFFFFFFFFu, r3x, o);
            r3y += __shfl_xor_sync(0xFFFFFFFFu, r3y, o);
            r3z += __shfl_xor_sync(0xFFFFFFFFu, r3z, o);
        }

        if (lane < 4 && kb + lane < count) {
            int nn  = (lane == 0) ? n0  : (lane == 1) ? n1  : (lane == 2) ? n2  : n3;
            float sv = (lane == 0) ? s0  : (lane == 1) ? s1  : (lane == 2) ? s2  : s3;
            float cx = (lane == 0) ? r0x : (lane == 1) ? r1x : (lane == 2) ? r2x : r3x;
            float cy = (lane == 0) ? r0y : (lane == 1) ? r1y : (lane == 2) ? r2y : r3y;
            float cz = (lane == 0) ? r0z : (lane == 1) ? r1z : (lane == 2) ? r2z : r3z;
            out_sig[nn] = sv + bsg;
            out_rgb[(size_t)nn * 3 + 0] = cx + br0;
            out_rgb[(size_t)nn * 3 + 1] = cy + br1;
            out_rgb[(size_t)nn * 3 + 2] = cz + br2;
        }
        __syncwarp();
    }
}

// ---------------------------------------------------------------- launch
extern "C" void kernel_launch(void* const* d_in, const int* in_sizes, int n_in,
                              void* d_out, int out_size) {
    const float* pts  = (const float*)d_in[0];
    const float* dirs = (const float*)d_in[1];
    const float* W1   = (const float*)d_in[2];
    const float* b1   = (const float*)d_in[3];
    const float* W2   = (const float*)d_in[4];
    const float* b2   = (const float*)d_in[5];
    const float* Wf   = (const float*)d_in[6];
    const float* bf   = (const float*)d_in[7];
    const float* Wsig = (const float*)d_in[8];
    const float* bsig = (const float*)d_in[9];
    const float* Wv   = (const float*)d_in[10];
    const float* bv   = (const float*)d_in[11];
    const float* Wrgb = (const float*)d_in[12];
    const float* brgb = (const float*)d_in[13];

    float* out_rgb = (float*)d_out;
    float* out_sig = (float*)d_out + (size_t)NPTS * 3;

    k_init<<<NEXP / 256, 256>>>(dirs);
    k_prep<<<NPTS / 256, 256>>>(pts);
    k_scan<<<1, 1024>>>();
    k_scatter<<<NPTS / 256, 256>>>();
    k_mlp<<<NEXP, 128>>>(W1, b1, W2, b2, Wf, bf, Wsig, bsig,
                         Wv, bv, Wrgb, brgb, out_rgb, out_sig);
}

// round 4
// speedup vs baseline: 1.5201x; 1.0526x over previous
#include <cuda_runtime.h>
#include <math.h>

#define NEXP   4096
#define NPTS   65536
#define NRAYS  1024
#define HID    32
#define IN_PTS 63
#define IN_DIR 27
#define IN_VIEW 59

// ---- scratch (no allocations allowed) ----
__device__ int    g_counts[NEXP];
__device__ int    g_offsets[NEXP];
__device__ int    g_expert[NPTS];
__device__ int    g_rank[NPTS];
__device__ int    g_sorted[NPTS];
__device__ int    g_flag;
__device__ float4 g_xp4[NPTS * 16];   // per-point xyz PE, 63 floats padded to 64
__device__ float4 g_xd4[NRAYS * 8];   // per-ray dir PE, 27 floats padded to 32

// ---------------------------------------------------------------- K0: zero counts + flag + dir PE
__global__ void k_init(const float* __restrict__ dirs) {
    int t = blockIdx.x * blockDim.x + threadIdx.x;   // 4096 threads
    g_counts[t] = 0;
    if (t == 0) g_flag = 0;
    if (t < NRAYS) {
        float x = dirs[t * 3 + 0];
        float y = dirs[t * 3 + 1];
        float z = dirs[t * 3 + 2];
        float row[32];
        row[0] = x; row[1] = y; row[2] = z;
        #pragma unroll
        for (int f = 0; f < 4; f++) {
            float m = (float)(1 << f);
            float s, c;
            sincosf(x * m, &s, &c); row[3 + 6 * f + 0] = s; row[6 + 6 * f + 0] = c;
            sincosf(y * m, &s, &c); row[3 + 6 * f + 1] = s; row[6 + 6 * f + 1] = c;
            sincosf(z * m, &s, &c); row[3 + 6 * f + 2] = s; row[6 + 6 * f + 2] = c;
        }
        row[27] = 0.f; row[28] = 0.f; row[29] = 0.f; row[30] = 0.f; row[31] = 0.f;
        float4* d = &g_xd4[t * 8];
        #pragma unroll
        for (int q = 0; q < 8; q++)
            d[q] = make_float4(row[4 * q], row[4 * q + 1], row[4 * q + 2], row[4 * q + 3]);
    }
}

// anchored double-angle PE for one axis: sincosf at l=0 and l=5 only
__device__ __forceinline__ void pe_axis(float x, float* row, int a) {
    float s, c;
    sincosf(x, &s, &c);
    row[3 + a] = s; row[6 + a] = c;
    float sl = s, cl = c;
    #pragma unroll
    for (int f = 1; f < 5; f++) {
        float ns = 2.0f * sl * cl;
        float nc = (cl - sl) * (cl + sl);
        row[3 + 6 * f + a] = ns; row[6 + 6 * f + a] = nc;
        sl = ns; cl = nc;
    }
    sincosf(x * 32.0f, &s, &c);
    row[3 + 30 + a] = s; row[6 + 30 + a] = c;
    sl = s; cl = c;
    #pragma unroll
    for (int f = 6; f < 10; f++) {
        float ns = 2.0f * sl * cl;
        float nc = (cl - sl) * (cl + sl);
        row[3 + 6 * f + a] = ns; row[6 + 6 * f + a] = nc;
        sl = ns; cl = nc;
    }
}

// ---------------------------------------------------------------- K1: classify + rank + xyz PE
__global__ void k_prep(const float* __restrict__ pts) {
    int n = blockIdx.x * blockDim.x + threadIdx.x;   // 65536 threads
    float x = pts[n * 3 + 0];
    float y = pts[n * 3 + 1];
    float z = pts[n * 3 + 2];

    float sx = fminf(fmaxf(((x + 1.5f) / 3.0f) * 16.0f, 0.0f), 15.0f);
    float sy = fminf(fmaxf(((y + 1.5f) / 3.0f) * 16.0f, 0.0f), 15.0f);
    float sz = fminf(fmaxf(((z + 1.5f) / 3.0f) * 16.0f, 0.0f), 15.0f);
    int e = ((int)sx) * 256 + ((int)sy) * 16 + (int)sz;
    g_expert[n] = e;
    g_rank[n] = atomicAdd(&g_counts[e], 1);

    float row[64];
    row[0] = x; row[1] = y; row[2] = z;
    pe_axis(x, row, 0);
    pe_axis(y, row, 1);
    pe_axis(z, row, 2);
    row[63] = 0.f;
    float4* d = &g_xp4[n * 16];
    #pragma unroll
    for (int q = 0; q < 16; q++)
        d[q] = make_float4(row[4 * q], row[4 * q + 1], row[4 * q + 2], row[4 * q + 3]);
}

// ---------------------------------------------------------------- K2: scan (block 0) + scatter (blocks 1..256)
__global__ void k_scan_scatter() {
    if (blockIdx.x == 0) {
        // exclusive scan of g_counts: 256 threads x 16 experts
        __shared__ int wsum[8];
        int tid = threadIdx.x;
        int base = tid * 16;
        int c[16];
        int local = 0;
        #pragma unroll
        for (int i = 0; i < 16; i++) { c[i] = g_counts[base + i]; local += c[i]; }
        int lane = tid & 31, w = tid >> 5;
        int v = local;
        #pragma unroll
        for (int off = 1; off < 32; off <<= 1) {
            int t = __shfl_up_sync(0xFFFFFFFFu, v, off);
            if (lane >= off) v += t;
        }
        if (lane == 31) wsum[w] = v;
        __syncthreads();
        if (w == 0 && lane < 8) {
            int s = wsum[lane];
            #pragma unroll
            for (int off = 1; off < 8; off <<= 1) {
                int t = __shfl_up_sync(0xFFu, s, off);
                if (lane >= off) s += t;
            }
            wsum[lane] = s;
        }
        __syncthreads();
        int prefix = v - local;
        if (w > 0) prefix += wsum[w - 1];
        int run = prefix;
        #pragma unroll
        for (int i = 0; i < 16; i++) { g_offsets[base + i] = run; run += c[i]; }
        // publish
        __threadfence();
        __syncthreads();
        if (tid == 0) atomicExch(&g_flag, 1);
    } else {
        int n = (blockIdx.x - 1) * 256 + threadIdx.x;
        // pre-load (independent of flag)
        int e = g_expert[n];
        int r = g_rank[n];
        // spin for offsets
        if (threadIdx.x == 0) {
            while (atomicAdd(&g_flag, 0) == 0) { __nanosleep(64); }
        }
        __syncthreads();
        __threadfence();
        g_sorted[g_offsets[e] + r] = n;
    }
}

// ---------------------------------------------------------------- K3: main MLP: 1 block per expert, 4 pts/warp
__global__ __launch_bounds__(128) void k_mlp(
    const float* __restrict__ W1, const float* __restrict__ b1,
    const float* __restrict__ W2, const float* __restrict__ b2,
    const float* __restrict__ Wf, const float* __restrict__ bf,
    const float* __restrict__ Wsig, const float* __restrict__ bsig,
    const float* __restrict__ Wv, const float* __restrict__ bv,
    const float* __restrict__ Wrgb, const float* __restrict__ brgb,
    float* __restrict__ out_rgb, float* __restrict__ out_sig)
{
    int e = blockIdx.x;
    int count = g_counts[e];
    if (count == 0) return;
    int start = g_offsets[e];

    __shared__ __align__(16) float sW1[IN_PTS * HID];
    __shared__ __align__(16) float sW2[HID * HID];
    __shared__ __align__(16) float sWf[HID * HID];
    __shared__ __align__(16) float sWv[IN_VIEW * HID];
    __shared__ float sWsig[HID];
    __shared__ float sWrgb[HID * 3];
    __shared__ float sb1[HID], sb2[HID], sbf[HID], sbv[HID];
    __shared__ float sconst[4];
    __shared__ __align__(16) float sxp[4][4 * 64];
    __shared__ __align__(16) float sxd[4][4 * 32];
    __shared__ __align__(16) float sh [4][4 * 32];

    int tid = threadIdx.x;
    {
        const float4* s1 = (const float4*)(W1 + (size_t)e * IN_PTS * HID);
        float4* d1 = (float4*)sW1;
        for (int i = tid; i < IN_PTS * HID / 4; i += 128) d1[i] = s1[i];
        const float4* s2 = (const float4*)(W2 + (size_t)e * HID * HID);
        float4* d2 = (float4*)sW2;
        for (int i = tid; i < HID * HID / 4; i += 128) d2[i] = s2[i];
        const float4* sf = (const float4*)(Wf + (size_t)e * HID * HID);
        float4* df = (float4*)sWf;
        for (int i = tid; i < HID * HID / 4; i += 128) df[i] = sf[i];
        const float4* sv = (const float4*)(Wv + (size_t)e * IN_VIEW * HID);
        float4* dv = (float4*)sWv;
        for (int i = tid; i < IN_VIEW * HID / 4; i += 128) dv[i] = sv[i];
        if (tid < HID) {
            sWsig[tid] = Wsig[(size_t)e * HID + tid];
            sb1[tid] = b1[(size_t)e * HID + tid];
            sb2[tid] = b2[(size_t)e * HID + tid];
            sbf[tid] = bf[(size_t)e * HID + tid];
            sbv[tid] = bv[(size_t)e * HID + tid];
        }
        if (tid >= 32 && tid < 128) sWrgb[tid - 32] = Wrgb[(size_t)e * HID * 3 + (tid - 32)];
        if (tid < 4) sconst[tid] = (tid == 0) ? bsig[e] : brgb[(size_t)e * 3 + tid - 1];
    }
    __syncthreads();

    int w = tid >> 5, lane = tid & 31;
    float* xpw = sxp[w];
    float* xdw = sxd[w];
    float* shw = sh[w];

    float bb1 = sb1[lane], bb2 = sb2[lane], bbf = sbf[lane], bbv = sbv[lane];
    float wsg = sWsig[lane];
    float wr0 = sWrgb[lane * 3 + 0], wr1 = sWrgb[lane * 3 + 1], wr2 = sWrgb[lane * 3 + 2];
    float bsg = sconst[0], br0 = sconst[1], br1 = sconst[2], br2 = sconst[3];

    for (int kb = w * 4; kb < count; kb += 16) {
        int n0 = g_sorted[start + min(kb + 0, count - 1)];
        int n1 = g_sorted[start + min(kb + 1, count - 1)];
        int n2 = g_sorted[start + min(kb + 2, count - 1)];
        int n3 = g_sorted[start + min(kb + 3, count - 1)];

        {
            int hp = lane >> 4, q = lane & 15;
            int na = (hp == 0) ? n0 : n1;
            int nb = (hp == 0) ? n2 : n3;
            ((float4*)xpw)[lane]      = g_xp4[(size_t)na * 16 + q];
            ((float4*)xpw)[lane + 32] = g_xp4[(size_t)nb * 16 + q];
        }
        {
            int p = lane >> 3, q = lane & 7;
            int nn = (p == 0) ? n0 : (p == 1) ? n1 : (p == 2) ? n2 : n3;
            ((float4*)xdw)[lane] = g_xd4[(size_t)(nn >> 6) * 8 + q];
        }
        __syncwarp();

        // ---- layer 1: 63 -> 32, relu ----
        float h0 = bb1, h1 = bb1, h2 = bb1, h3 = bb1;
        #pragma unroll
        for (int i = 0; i < 60; i += 4) {
            float wa = sW1[(i + 0) * 32 + lane];
            float wb = sW1[(i + 1) * 32 + lane];
            float wc = sW1[(i + 2) * 32 + lane];
            float wd = sW1[(i + 3) * 32 + lane];
            float4 x0 = *(const float4*)&xpw[0 * 64 + i];
            float4 x1 = *(const float4*)&xpw[1 * 64 + i];
            float4 x2 = *(const float4*)&xpw[2 * 64 + i];
            float4 x3 = *(const float4*)&xpw[3 * 64 + i];
            h0 = fmaf(x0.x, wa, h0); h0 = fmaf(x0.y, wb, h0); h0 = fmaf(x0.z, wc, h0); h0 = fmaf(x0.w, wd, h0);
            h1 = fmaf(x1.x, wa, h1); h1 = fmaf(x1.y, wb, h1); h1 = fmaf(x1.z, wc, h1); h1 = fmaf(x1.w, wd, h1);
            h2 = fmaf(x2.x, wa, h2); h2 = fmaf(x2.y, wb, h2); h2 = fmaf(x2.z, wc, h2); h2 = fmaf(x2.w, wd, h2);
            h3 = fmaf(x3.x, wa, h3); h3 = fmaf(x3.y, wb, h3); h3 = fmaf(x3.z, wc, h3); h3 = fmaf(x3.w, wd, h3);
        }
        #pragma unroll
        for (int i = 60; i < 63; i++) {
            float wa = sW1[i * 32 + lane];
            h0 = fmaf(xpw[0 * 64 + i], wa, h0);
            h1 = fmaf(xpw[1 * 64 + i], wa, h1);
            h2 = fmaf(xpw[2 * 64 + i], wa, h2);
            h3 = fmaf(xpw[3 * 64 + i], wa, h3);
        }
        h0 = fmaxf(h0, 0.f); h1 = fmaxf(h1, 0.f); h2 = fmaxf(h2, 0.f); h3 = fmaxf(h3, 0.f);
        shw[0 * 32 + lane] = h0; shw[1 * 32 + lane] = h1;
        shw[2 * 32 + lane] = h2; shw[3 * 32 + lane] = h3;
        __syncwarp();

        // ---- layer 2: 32 -> 32, relu ----
        float g0 = bb2, g1 = bb2, g2 = bb2, g3 = bb2;
        #pragma unroll
        for (int i = 0; i < 32; i += 4) {
            float wa = sW2[(i + 0) * 32 + lane];
            float wb = sW2[(i + 1) * 32 + lane];
            float wc = sW2[(i + 2) * 32 + lane];
            float wd = sW2[(i + 3) * 32 + lane];
            float4 x0 = *(const float4*)&shw[0 * 32 + i];
            float4 x1 = *(const float4*)&shw[1 * 32 + i];
            float4 x2 = *(const float4*)&shw[2 * 32 + i];
            float4 x3 = *(const float4*)&shw[3 * 32 + i];
            g0 = fmaf(x0.x, wa, g0); g0 = fmaf(x0.y, wb, g0); g0 = fmaf(x0.z, wc, g0); g0 = fmaf(x0.w, wd, g0);
            g1 = fmaf(x1.x, wa, g1); g1 = fmaf(x1.y, wb, g1); g1 = fmaf(x1.z, wc, g1); g1 = fmaf(x1.w, wd, g1);
            g2 = fmaf(x2.x, wa, g2); g2 = fmaf(x2.y, wb, g2); g2 = fmaf(x2.z, wc, g2); g2 = fmaf(x2.w, wd, g2);
            g3 = fmaf(x3.x, wa, g3); g3 = fmaf(x3.y, wb, g3); g3 = fmaf(x3.z, wc, g3); g3 = fmaf(x3.w, wd, g3);
        }
        g0 = fmaxf(g0, 0.f); g1 = fmaxf(g1, 0.f); g2 = fmaxf(g2, 0.f); g3 = fmaxf(g3, 0.f);

        float s0 = g0 * wsg, s1 = g1 * wsg, s2 = g2 * wsg, s3 = g3 * wsg;

        __syncwarp();
        shw[0 * 32 + lane] = g0; shw[1 * 32 + lane] = g1;
        shw[2 * 32 + lane] = g2; shw[3 * 32 + lane] = g3;
        __syncwarp();

        // ---- feature: 32 -> 32 (linear) ----
        float f0 = bbf, f1 = bbf, f2 = bbf, f3 = bbf;
        #pragma unroll
        for (int i = 0; i < 32; i += 4) {
            float wa = sWf[(i + 0) * 32 + lane];
            float wb = sWf[(i + 1) * 32 + lane];
            float wc = sWf[(i + 2) * 32 + lane];
            float wd = sWf[(i + 3) * 32 + lane];
            float4 x0 = *(const float4*)&shw[0 * 32 + i];
            float4 x1 = *(const float4*)&shw[1 * 32 + i];
            float4 x2 = *(const float4*)&shw[2 * 32 + i];
            float4 x3 = *(const float4*)&shw[3 * 32 + i];
            f0 = fmaf(x0.x, wa, f0); f0 = fmaf(x0.y, wb, f0); f0 = fmaf(x0.z, wc, f0); f0 = fmaf(x0.w, wd, f0);
            f1 = fmaf(x1.x, wa, f1); f1 = fmaf(x1.y, wb, f1); f1 = fmaf(x1.z, wc, f1); f1 = fmaf(x1.w, wd, f1);
            f2 = fmaf(x2.x, wa, f2); f2 = fmaf(x2.y, wb, f2); f2 = fmaf(x2.z, wc, f2); f2 = fmaf(x2.w, wd, f2);
            f3 = fmaf(x3.x, wa, f3); f3 = fmaf(x3.y, wb, f3); f3 = fmaf(x3.z, wc, f3); f3 = fmaf(x3.w, wd, f3);
        }
        __syncwarp();
        shw[0 * 32 + lane] = f0; shw[1 * 32 + lane] = f1;
        shw[2 * 32 + lane] = f2; shw[3 * 32 + lane] = f3;
        __syncwarp();

        // ---- view layer: [feat(32), xd(27)] -> 32, relu ----
        float v0 = bbv, v1 = bbv, v2 = bbv, v3 = bbv;
        #pragma unroll
        for (int i = 0; i < 32; i += 4) {
            float wa = sWv[(i + 0) * 32 + lane];
            float wb = sWv[(i + 1) * 32 + lane];
            float wc = sWv[(i + 2) * 32 + lane];
            float wd = sWv[(i + 3) * 32 + lane];
            float4 x0 = *(const float4*)&shw[0 * 32 + i];
            float4 x1 = *(const float4*)&shw[1 * 32 + i];
            float4 x2 = *(const float4*)&shw[2 * 32 + i];
            float4 x3 = *(const float4*)&shw[3 * 32 + i];
            v0 = fmaf(x0.x, wa, v0); v0 = fmaf(x0.y, wb, v0); v0 = fmaf(x0.z, wc, v0); v0 = fmaf(x0.w, wd, v0);
            v1 = fmaf(x1.x, wa, v1); v1 = fmaf(x1.y, wb, v1); v1 = fmaf(x1.z, wc, v1); v1 = fmaf(x1.w, wd, v1);
            v2 = fmaf(x2.x, wa, v2); v2 = fmaf(x2.y, wb, v2); v2 = fmaf(x2.z, wc, v2); v2 = fmaf(x2.w, wd, v2);
            v3 = fmaf(x3.x, wa, v3); v3 = fmaf(x3.y, wb, v3); v3 = fmaf(x3.z, wc, v3); v3 = fmaf(x3.w, wd, v3);
        }
        #pragma unroll
        for (int j = 0; j < 24; j += 4) {
            float wa = sWv[(HID + j + 0) * 32 + lane];
            float wb = sWv[(HID + j + 1) * 32 + lane];
            float wc = sWv[(HID + j + 2) * 32 + lane];
            float wd = sWv[(HID + j + 3) * 32 + lane];
            float4 x0 = *(const float4*)&xdw[0 * 32 + j];
            float4 x1 = *(const float4*)&xdw[1 * 32 + j];
            float4 x2 = *(const float4*)&xdw[2 * 32 + j];
            float4 x3 = *(const float4*)&xdw[3 * 32 + j];
            v0 = fmaf(x0.x, wa, v0); v0 = fmaf(x0.y, wb, v0); v0 = fmaf(x0.z, wc, v0); v0 = fmaf(x0.w, wd, v0);
            v1 = fmaf(x1.x, wa, v1); v1 = fmaf(x1.y, wb, v1); v1 = fmaf(x1.z, wc, v1); v1 = fmaf(x1.w, wd, v1);
            v2 = fmaf(x2.x, wa, v2); v2 = fmaf(x2.y, wb, v2); v2 = fmaf(x2.z, wc, v2); v2 = fmaf(x2.w, wd, v2);
            v3 = fmaf(x3.x, wa, v3); v3 = fmaf(x3.y, wb, v3); v3 = fmaf(x3.z, wc, v3); v3 = fmaf(x3.w, wd, v3);
        }
        #pragma unroll
        for (int j = 24; j < IN_DIR; j++) {
            float wa = sWv[(HID + j) * 32 + lane];
            v0 = fmaf(xdw[0 * 32 + j], wa, v0);
            v1 = fmaf(xdw[1 * 32 + j], wa, v1);
            v2 = fmaf(xdw[2 * 32 + j], wa, v2);
            v3 = fmaf(xdw[3 * 32 + j], wa, v3);
        }
        v0 = fmaxf(v0, 0.f); v1 = fmaxf(v1, 0.f); v2 = fmaxf(v2, 0.f); v3 = fmaxf(v3, 0.f);

        float r0x = v0 * wr0, r0y = v0 * wr1, r0z = v0 * wr2;
        float r1x = v1 * wr0, r1y = v1 * wr1, r1z = v1 * wr2;
        float r2x = v2 * wr0, r2y = v2 * wr1, r2z = v2 * wr2;
        float r3x = v3 * wr0, r3y = v3 * wr1, r3z = v3 * wr2;

        #pragma unroll
        for (int o = 16; o > 0; o >>= 1) {
            s0  += __shfl_xor_sync(0xFFFFFFFFu, s0,  o);
            s1  += __shfl_xor_sync(0xFFFFFFFFu, s1,  o);
            s2  += __shfl_xor_sync(0xFFFFFFFFu, s2,  o);
            s3  += __shfl_xor_sync(0xFFFFFFFFu, s3,  o);
            r0x += __shfl_xor_sync(0xFFFFFFFFu, r0x, o);
            r0y += __shfl_xor_sync(0xFFFFFFFFu, r0y, o);
            r0z += __shfl_xor_sync(0xFFFFFFFFu, r0z, o);
            r1x += __shfl_xor_sync(0xFFFFFFFFu, r1x, o);
            r1y += __shfl_xor_sync(0xFFFFFFFFu, r1y, o);
            r1z += __shfl_xor_sync(0xFFFFFFFFu, r1z, o);
            r2x += __shfl_xor_sync(0xFFFFFFFFu, r2x, o);
            r2y += __shfl_xor_sync(0xFFFFFFFFu, r2y, o);
            r2z += __shfl_xor_sync(0xFFFFFFFFu, r2z, o);
            r3x += __shfl_xor_sync(0xFFFFFFFFu, r3x, o);
            r3y += __shfl_xor_sync(0xFFFFFFFFu, r3y, o);
            r3z += __shfl_xor_sync(0xFFFFFFFFu, r3z, o);
        }

        if (lane < 4 && kb + lane < count) {
            int nn  = (lane == 0) ? n0  : (lane == 1) ? n1  : (lane == 2) ? n2  : n3;
            float sv = (lane == 0) ? s0  : (lane == 1) ? s1  : (lane == 2) ? s2  : s3;
            float cx = (lane == 0) ? r0x : (lane == 1) ? r1x : (lane == 2) ? r2x : r3x;
            float cy = (lane == 0) ? r0y : (lane == 1) ? r1y : (lane == 2) ? r2y : r3y;
            float cz = (lane == 0) ? r0z : (lane == 1) ? r1z : (lane == 2) ? r2z : r3z;
            out_sig[nn] = sv + bsg;
            out_rgb[(size_t)nn * 3 + 0] = cx + br0;
            out_rgb[(size_t)nn * 3 + 1] = cy + br1;
            out_rgb[(size_t)nn * 3 + 2] = cz + br2;
        }
        __syncwarp();
    }
}

// ---------------------------------------------------------------- launch
extern "C" void kernel_launch(void* const* d_in, const int* in_sizes, int n_in,
                              void* d_out, int out_size) {
    const float* pts  = (const float*)d_in[0];
    const float* dirs = (const float*)d_in[1];
    const float* W1   = (const float*)d_in[2];
    const float* b1   = (const float*)d_in[3];
    const float* W2   = (const float*)d_in[4];
    const float* b2   = (const float*)d_in[5];
    const float* Wf   = (const float*)d_in[6];
    const float* bf   = (const float*)d_in[7];
    const float* Wsig = (const float*)d_in[8];
    const float* bsig = (const float*)d_in[9];
    const float* Wv   = (const float*)d_in[10];
    const float* bv   = (const float*)d_in[11];
    const float* Wrgb = (const float*)d_in[12];
    const float* brgb = (const float*)d_in[13];

    float* out_rgb = (float*)d_out;
    float* out_sig = (float*)d_out + (size_t)NPTS * 3;

    k_init<<<NEXP / 256, 256>>>(dirs);
    k_prep<<<NPTS / 256, 256>>>(pts);
    k_scan_scatter<<<257, 256>>>();
    k_mlp<<<NEXP, 128>>>(W1, b1, W2, b2, Wf, bf, Wsig, bsig,
                         Wv, bv, Wrgb, brgb, out_rgb, out_sig);
}

// round 7
// speedup vs baseline: 1.5831x; 1.0415x over previous
#include <cuda_runtime.h>
#include <cstdint>
#include <math.h>

#define NEXP   4096
#define NPTS   65536
#define NRAYS  1024
#define HID    32
#define IN_PTS 63
#define IN_DIR 27
#define IN_VIEW 59

// packed per-expert weight buffer layout (floats)
#define OFF_W1   0
#define OFF_W2   2016
#define OFF_WF   3040
#define OFF_WV   4064
#define OFF_WSIG 5952
#define OFF_WRGB 5984
#define OFF_B1   6080
#define OFF_B2   6112
#define OFF_BF   6144
#define OFF_BV   6176
#define BUF_FLOATS 6208
#define GRID_MLP 444
#define SMEM_FLOATS (2 * BUF_FLOATS + 8 * 256 + 8 * 128 + 8 * 128)   // 16512
#define SMEM_BYTES  (SMEM_FLOATS * 4)                                // 66048

// ---- scratch (no allocations allowed) ----
__device__ int    g_counts[NEXP];
__device__ int    g_offsets[NEXP];
__device__ int    g_expert[NPTS];
__device__ int    g_rank[NPTS];
__device__ int    g_sorted[NPTS];
__device__ int    g_flag;
__device__ float4 g_xp4[NPTS * 16];
__device__ float4 g_xd4[NRAYS * 8];

// ---------------------------------------------------------------- K0: zero counts + flag + dir PE
__global__ void k_init(const float* __restrict__ dirs) {
    int t = blockIdx.x * blockDim.x + threadIdx.x;
    g_counts[t] = 0;
    if (t == 0) g_flag = 0;
    if (t < NRAYS) {
        float x = dirs[t * 3 + 0];
        float y = dirs[t * 3 + 1];
        float z = dirs[t * 3 + 2];
        float row[32];
        row[0] = x; row[1] = y; row[2] = z;
        #pragma unroll
        for (int f = 0; f < 4; f++) {
            float m = (float)(1 << f);
            float s, c;
            sincosf(x * m, &s, &c); row[3 + 6 * f + 0] = s; row[6 + 6 * f + 0] = c;
            sincosf(y * m, &s, &c); row[3 + 6 * f + 1] = s; row[6 + 6 * f + 1] = c;
            sincosf(z * m, &s, &c); row[3 + 6 * f + 2] = s; row[6 + 6 * f + 2] = c;
        }
        row[27] = 0.f; row[28] = 0.f; row[29] = 0.f; row[30] = 0.f; row[31] = 0.f;
        float4* d = &g_xd4[t * 8];
        #pragma unroll
        for (int q = 0; q < 8; q++)
            d[q] = make_float4(row[4 * q], row[4 * q + 1], row[4 * q + 2], row[4 * q + 3]);
    }
}

// anchored double-angle PE for one axis
__device__ __forceinline__ void pe_axis(float x, float* row, int a) {
    float s, c;
    sincosf(x, &s, &c);
    row[3 + a] = s; row[6 + a] = c;
    float sl = s, cl = c;
    #pragma unroll
    for (int f = 1; f < 5; f++) {
        float ns = 2.0f * sl * cl;
        float nc = (cl - sl) * (cl + sl);
        row[3 + 6 * f + a] = ns; row[6 + 6 * f + a] = nc;
        sl = ns; cl = nc;
    }
    sincosf(x * 32.0f, &s, &c);
    row[3 + 30 + a] = s; row[6 + 30 + a] = c;
    sl = s; cl = c;
    #pragma unroll
    for (int f = 6; f < 10; f++) {
        float ns = 2.0f * sl * cl;
        float nc = (cl - sl) * (cl + sl);
        row[3 + 6 * f + a] = ns; row[6 + 6 * f + a] = nc;
        sl = ns; cl = nc;
    }
}

// ---------------------------------------------------------------- K1: classify + rank + xyz PE
__global__ void k_prep(const float* __restrict__ pts) {
    int n = blockIdx.x * blockDim.x + threadIdx.x;
    float x = pts[n * 3 + 0];
    float y = pts[n * 3 + 1];
    float z = pts[n * 3 + 2];

    float sx = fminf(fmaxf(((x + 1.5f) / 3.0f) * 16.0f, 0.0f), 15.0f);
    float sy = fminf(fmaxf(((y + 1.5f) / 3.0f) * 16.0f, 0.0f), 15.0f);
    float sz = fminf(fmaxf(((z + 1.5f) / 3.0f) * 16.0f, 0.0f), 15.0f);
    int e = ((int)sx) * 256 + ((int)sy) * 16 + (int)sz;
    g_expert[n] = e;
    g_rank[n] = atomicAdd(&g_counts[e], 1);

    float row[64];
    row[0] = x; row[1] = y; row[2] = z;
    pe_axis(x, row, 0);
    pe_axis(y, row, 1);
    pe_axis(z, row, 2);
    row[63] = 0.f;
    float4* d = &g_xp4[n * 16];
    #pragma unroll
    for (int q = 0; q < 16; q++)
        d[q] = make_float4(row[4 * q], row[4 * q + 1], row[4 * q + 2], row[4 * q + 3]);
}

// ---------------------------------------------------------------- K2: scan (block 0) + scatter (blocks 1..256)
__global__ void k_scan_scatter() {
    if (blockIdx.x == 0) {
        __shared__ int wsum[8];
        int tid = threadIdx.x;
        int base = tid * 16;
        int c[16];
        int local = 0;
        #pragma unroll
        for (int i = 0; i < 16; i++) { c[i] = g_counts[base + i]; local += c[i]; }
        int lane = tid & 31, w = tid >> 5;
        int v = local;
        #pragma unroll
        for (int off = 1; off < 32; off <<= 1) {
            int t = __shfl_up_sync(0xFFFFFFFFu, v, off);
            if (lane >= off) v += t;
        }
        if (lane == 31) wsum[w] = v;
        __syncthreads();
        if (w == 0 && lane < 8) {
            int s = wsum[lane];
            #pragma unroll
            for (int off = 1; off < 8; off <<= 1) {
                int t = __shfl_up_sync(0xFFu, s, off);
                if (lane >= off) s += t;
            }
            wsum[lane] = s;
        }
        __syncthreads();
        int prefix = v - local;
        if (w > 0) prefix += wsum[w - 1];
        int run = prefix;
        #pragma unroll
        for (int i = 0; i < 16; i++) { g_offsets[base + i] = run; run += c[i]; }
        __threadfence();
        __syncthreads();
        if (tid == 0) atomicExch(&g_flag, 1);
    } else {
        int n = (blockIdx.x - 1) * 256 + threadIdx.x;
        int e = g_expert[n];
        int r = g_rank[n];
        if (threadIdx.x == 0) {
            while (atomicAdd(&g_flag, 0) == 0) { __nanosleep(64); }
        }
        __syncthreads();
        __threadfence();
        g_sorted[g_offsets[e] + r] = n;
    }
}

// ---------------------------------------------------------------- cp.async helpers
__device__ __forceinline__ void cp16(float* dst, const float* src) {
    unsigned int s = (unsigned int)__cvta_generic_to_shared(dst);
    asm volatile("cp.async.cg.shared.global [%0], [%1], 16;" :: "r"(s), "l"(src));
}
__device__ __forceinline__ void cp_commit() { asm volatile("cp.async.commit_group;"); }
__device__ __forceinline__ void cp_wait1()  { asm volatile("cp.async.wait_group 1;"); }
__device__ __forceinline__ void cp_wait0()  { asm volatile("cp.async.wait_group 0;"); }

__device__ __forceinline__ void prefetch_expert(
    int e, float* dst, int tid,
    const float* __restrict__ W1, const float* __restrict__ W2,
    const float* __restrict__ Wf, const float* __restrict__ Wv,
    const float* __restrict__ Wsig, const float* __restrict__ Wrgb,
    const float* __restrict__ b1, const float* __restrict__ b2,
    const float* __restrict__ bf, const float* __restrict__ bv)
{
    const float* s;
    s = W1 + (size_t)e * 2016;
    for (int c = tid; c < 504; c += 256) cp16(dst + OFF_W1 + c * 4, s + c * 4);
    s = W2 + (size_t)e * 1024;
    for (int c = tid; c < 256; c += 256) cp16(dst + OFF_W2 + c * 4, s + c * 4);
    s = Wf + (size_t)e * 1024;
    for (int c = tid; c < 256; c += 256) cp16(dst + OFF_WF + c * 4, s + c * 4);
    s = Wv + (size_t)e * 1888;
    for (int c = tid; c < 472; c += 256) cp16(dst + OFF_WV + c * 4, s + c * 4);
    if (tid < 8)  cp16(dst + OFF_WSIG + tid * 4, Wsig + (size_t)e * 32 + tid * 4);
    if (tid >= 8 && tid < 32) cp16(dst + OFF_WRGB + (tid - 8) * 4, Wrgb + (size_t)e * 96 + (tid - 8) * 4);
    if (tid >= 32 && tid < 40) cp16(dst + OFF_B1 + (tid - 32) * 4, b1 + (size_t)e * 32 + (tid - 32) * 4);
    if (tid >= 40 && tid < 48) cp16(dst + OFF_B2 + (tid - 40) * 4, b2 + (size_t)e * 32 + (tid - 40) * 4);
    if (tid >= 48 && tid < 56) cp16(dst + OFF_BF + (tid - 48) * 4, bf + (size_t)e * 32 + (tid - 48) * 4);
    if (tid >= 56 && tid < 64) cp16(dst + OFF_BV + (tid - 56) * 4, bv + (size_t)e * 32 + (tid - 56) * 4);
}

// ---------------------------------------------------------------- K3: persistent pipelined MLP
__global__ __launch_bounds__(256, 3) void k_mlp(
    const float* __restrict__ W1, const float* __restrict__ b1,
    const float* __restrict__ W2, const float* __restrict__ b2,
    const float* __restrict__ Wf, const float* __restrict__ bf,
    const float* __restrict__ Wsig, const float* __restrict__ bsig,
    const float* __restrict__ Wv, const float* __restrict__ bv,
    const float* __restrict__ Wrgb, const float* __restrict__ brgb,
    float* __restrict__ out_rgb, float* __restrict__ out_sig)
{
    extern __shared__ __align__(16) float smem[];
    float* act = smem + 2 * BUF_FLOATS;
    int tid = threadIdx.x;
    int w = tid >> 5, lane = tid & 31;
    float* xpw = act + w * 256;
    float* xdw = act + 8 * 256 + w * 128;
    float* shw = act + 8 * 256 + 8 * 128 + w * 128;

    // first nonempty expert for this block
    int e_cur = -1;
    for (int e = blockIdx.x; e < NEXP; e += GRID_MLP)
        if (g_counts[e] > 0) { e_cur = e; break; }
    if (e_cur < 0) return;

    prefetch_expert(e_cur, smem, tid, W1, W2, Wf, Wv, Wsig, Wrgb, b1, b2, bf, bv);
    cp_commit();
    int parity = 0;

    while (e_cur >= 0) {
        int e_next = -1;
        for (int e = e_cur + GRID_MLP; e < NEXP; e += GRID_MLP)
            if (g_counts[e] > 0) { e_next = e; break; }
        if (e_next >= 0) {
            prefetch_expert(e_next, smem + (1 - parity) * BUF_FLOATS, tid,
                            W1, W2, Wf, Wv, Wsig, Wrgb, b1, b2, bf, bv);
            cp_commit();
            cp_wait1();
        } else {
            cp_wait0();
        }
        __syncthreads();

        // ---------------- compute expert e_cur from buffer ----------------
        {
            const float* bw = smem + parity * BUF_FLOATS;
            int e = e_cur;
            int count = g_counts[e];
            int start = g_offsets[e];

            float bb1 = bw[OFF_B1 + lane], bb2 = bw[OFF_B2 + lane];
            float bbf = bw[OFF_BF + lane], bbv = bw[OFF_BV + lane];
            float wsg = bw[OFF_WSIG + lane];
            float wr0 = bw[OFF_WRGB + lane * 3 + 0];
            float wr1 = bw[OFF_WRGB + lane * 3 + 1];
            float wr2 = bw[OFF_WRGB + lane * 3 + 2];
            float bsg = __ldg(&bsig[e]);
            float br0 = __ldg(&brgb[(size_t)e * 3 + 0]);
            float br1 = __ldg(&brgb[(size_t)e * 3 + 1]);
            float br2 = __ldg(&brgb[(size_t)e * 3 + 2]);
            const float* sW1 = bw + OFF_W1;
            const float* sW2 = bw + OFF_W2;
            const float* sWf = bw + OFF_WF;
            const float* sWv = bw + OFF_WV;

            for (int kb = w * 4; kb < count; kb += 32) {
                int n0 = g_sorted[start + min(kb + 0, count - 1)];
                int n1 = g_sorted[start + min(kb + 1, count - 1)];
                int n2 = g_sorted[start + min(kb + 2, count - 1)];
                int n3 = g_sorted[start + min(kb + 3, count - 1)];

                {
                    int hp = lane >> 4, q = lane & 15;
                    int na = (hp == 0) ? n0 : n1;
                    int nb = (hp == 0) ? n2 : n3;
                    ((float4*)xpw)[lane]      = g_xp4[(size_t)na * 16 + q];
                    ((float4*)xpw)[lane + 32] = g_xp4[(size_t)nb * 16 + q];
                }
                {
                    int p = lane >> 3, q = lane & 7;
                    int nn = (p == 0) ? n0 : (p == 1) ? n1 : (p == 2) ? n2 : n3;
                    ((float4*)xdw)[lane] = g_xd4[(size_t)(nn >> 6) * 8 + q];
                }
                __syncwarp();

                // layer 1: 63 -> 32, relu
                float h0 = bb1, h1 = bb1, h2 = bb1, h3 = bb1;
                #pragma unroll
                for (int i = 0; i < 60; i += 4) {
                    float wa = sW1[(i + 0) * 32 + lane];
                    float wb = sW1[(i + 1) * 32 + lane];
                    float wc = sW1[(i + 2) * 32 + lane];
                    float wd = sW1[(i + 3) * 32 + lane];
                    float4 x0 = *(const float4*)&xpw[0 * 64 + i];
                    float4 x1 = *(const float4*)&xpw[1 * 64 + i];
                    float4 x2 = *(const float4*)&xpw[2 * 64 + i];
                    float4 x3 = *(const float4*)&xpw[3 * 64 + i];
                    h0 = fmaf(x0.x, wa, h0); h0 = fmaf(x0.y, wb, h0); h0 = fmaf(x0.z, wc, h0); h0 = fmaf(x0.w, wd, h0);
                    h1 = fmaf(x1.x, wa, h1); h1 = fmaf(x1.y, wb, h1); h1 = fmaf(x1.z, wc, h1); h1 = fmaf(x1.w, wd, h1);
                    h2 = fmaf(x2.x, wa, h2); h2 = fmaf(x2.y, wb, h2); h2 = fmaf(x2.z, wc, h2); h2 = fmaf(x2.w, wd, h2);
                    h3 = fmaf(x3.x, wa, h3); h3 = fmaf(x3.y, wb, h3); h3 = fmaf(x3.z, wc, h3); h3 = fmaf(x3.w, wd, h3);
                }
                #pragma unroll
                for (int i = 60; i < 63; i++) {
                    float wa = sW1[i * 32 + lane];
                    h0 = fmaf(xpw[0 * 64 + i], wa, h0);
                    h1 = fmaf(xpw[1 * 64 + i], wa, h1);
                    h2 = fmaf(xpw[2 * 64 + i], wa, h2);
                    h3 = fmaf(xpw[3 * 64 + i], wa, h3);
                }
                h0 = fmaxf(h0, 0.f); h1 = fmaxf(h1, 0.f); h2 = fmaxf(h2, 0.f); h3 = fmaxf(h3, 0.f);
                shw[0 * 32 + lane] = h0; shw[1 * 32 + lane] = h1;
                shw[2 * 32 + lane] = h2; shw[3 * 32 + lane] = h3;
                __syncwarp();

                // layer 2: 32 -> 32, relu
                float g0 = bb2, g1 = bb2, g2 = bb2, g3 = bb2;
                #pragma unroll
                for (int i = 0; i < 32; i += 4) {
                    float wa = sW2[(i + 0) * 32 + lane];
                    float wb = sW2[(i + 1) * 32 + lane];
                    float wc = sW2[(i + 2) * 32 + lane];
                    float wd = sW2[(i + 3) * 32 + lane];
                    float4 x0 = *(const float4*)&shw[0 * 32 + i];
                    float4 x1 = *(const float4*)&shw[1 * 32 + i];
                    float4 x2 = *(const float4*)&shw[2 * 32 + i];
                    float4 x3 = *(const float4*)&shw[3 * 32 + i];
                    g0 = fmaf(x0.x, wa, g0); g0 = fmaf(x0.y, wb, g0); g0 = fmaf(x0.z, wc, g0); g0 = fmaf(x0.w, wd, g0);
                    g1 = fmaf(x1.x, wa, g1); g1 = fmaf(x1.y, wb, g1); g1 = fmaf(x1.z, wc, g1); g1 = fmaf(x1.w, wd, g1);
                    g2 = fmaf(x2.x, wa, g2); g2 = fmaf(x2.y, wb, g2); g2 = fmaf(x2.z, wc, g2); g2 = fmaf(x2.w, wd, g2);
                    g3 = fmaf(x3.x, wa, g3); g3 = fmaf(x3.y, wb, g3); g3 = fmaf(x3.z, wc, g3); g3 = fmaf(x3.w, wd, g3);
                }
                g0 = fmaxf(g0, 0.f); g1 = fmaxf(g1, 0.f); g2 = fmaxf(g2, 0.f); g3 = fmaxf(g3, 0.f);

                float s0 = g0 * wsg, s1 = g1 * wsg, s2 = g2 * wsg, s3 = g3 * wsg;

                __syncwarp();
                shw[0 * 32 + lane] = g0; shw[1 * 32 + lane] = g1;
                shw[2 * 32 + lane] = g2; shw[3 * 32 + lane] = g3;
                __syncwarp();

                // feature: 32 -> 32 (linear)
                float f0 = bbf, f1 = bbf, f2 = bbf, f3 = bbf;
                #pragma unroll
                for (int i = 0; i < 32; i += 4) {
                    float wa = sWf[(i + 0) * 32 + lane];
                    float wb = sWf[(i + 1) * 32 + lane];
                    float wc = sWf[(i + 2) * 32 + lane];
                    float wd = sWf[(i + 3) * 32 + lane];
                    float4 x0 = *(const float4*)&shw[0 * 32 + i];
                    float4 x1 = *(const float4*)&shw[1 * 32 + i];
                    float4 x2 = *(const float4*)&shw[2 * 32 + i];
                    float4 x3 = *(const float4*)&shw[3 * 32 + i];
                    f0 = fmaf(x0.x, wa, f0); f0 = fmaf(x0.y, wb, f0); f0 = fmaf(x0.z, wc, f0); f0 = fmaf(x0.w, wd, f0);
                    f1 = fmaf(x1.x, wa, f1); f1 = fmaf(x1.y, wb, f1); f1 = fmaf(x1.z, wc, f1); f1 = fmaf(x1.w, wd, f1);
                    f2 = fmaf(x2.x, wa, f2); f2 = fmaf(x2.y, wb, f2); f2 = fmaf(x2.z, wc, f2); f2 = fmaf(x2.w, wd, f2);
                    f3 = fmaf(x3.x, wa, f3); f3 = fmaf(x3.y, wb, f3); f3 = fmaf(x3.z, wc, f3); f3 = fmaf(x3.w, wd, f3);
                }
                __syncwarp();
                shw[0 * 32 + lane] = f0; shw[1 * 32 + lane] = f1;
                shw[2 * 32 + lane] = f2; shw[3 * 32 + lane] = f3;
                __syncwarp();

                // view layer: [feat(32), xd(27)] -> 32, relu
                float v0 = bbv, v1 = bbv, v2 = bbv, v3 = bbv;
                #pragma unroll
                for (int i = 0; i < 32; i += 4) {
                    float wa = sWv[(i + 0) * 32 + lane];
                    float wb = sWv[(i + 1) * 32 + lane];
                    float wc = sWv[(i + 2) * 32 + lane];
                    float wd = sWv[(i + 3) * 32 + lane];
                    float4 x0 = *(const float4*)&shw[0 * 32 + i];
                    float4 x1 = *(const float4*)&shw[1 * 32 + i];
                    float4 x2 = *(const float4*)&shw[2 * 32 + i];
                    float4 x3 = *(const float4*)&shw[3 * 32 + i];
                    v0 = fmaf(x0.x, wa, v0); v0 = fmaf(x0.y, wb, v0); v0 = fmaf(x0.z, wc, v0); v0 = fmaf(x0.w, wd, v0);
                    v1 = fmaf(x1.x, wa, v1); v1 = fmaf(x1.y, wb, v1); v1 = fmaf(x1.z, wc, v1); v1 = fmaf(x1.w, wd, v1);
                    v2 = fmaf(x2.x, wa, v2); v2 = fmaf(x2.y, wb, v2); v2 = fmaf(x2.z, wc, v2); v2 = fmaf(x2.w, wd, v2);
                    v3 = fmaf(x3.x, wa, v3); v3 = fmaf(x3.y, wb, v3); v3 = fmaf(x3.z, wc, v3); v3 = fmaf(x3.w, wd, v3);
                }
                #pragma unroll
                for (int j = 0; j < 24; j += 4) {
                    float wa = sWv[(HID + j + 0) * 32 + lane];
                    float wb = sWv[(HID + j + 1) * 32 + lane];
                    float wc = sWv[(HID + j + 2) * 32 + lane];
                    float wd = sWv[(HID + j + 3) * 32 + lane];
                    float4 x0 = *(const float4*)&xdw[0 * 32 + j];
                    float4 x1 = *(const float4*)&xdw[1 * 32 + j];
                    float4 x2 = *(const float4*)&xdw[2 * 32 + j];
                    float4 x3 = *(const float4*)&xdw[3 * 32 + j];
                    v0 = fmaf(x0.x, wa, v0); v0 = fmaf(x0.y, wb, v0); v0 = fmaf(x0.z, wc, v0); v0 = fmaf(x0.w, wd, v0);
                    v1 = fmaf(x1.x, wa, v1); v1 = fmaf(x1.y, wb, v1); v1 = fmaf(x1.z, wc, v1); v1 = fmaf(x1.w, wd, v1);
                    v2 = fmaf(x2.x, wa, v2); v2 = fmaf(x2.y, wb, v2); v2 = fmaf(x2.z, wc, v2); v2 = fmaf(x2.w, wd, v2);
                    v3 = fmaf(x3.x, wa, v3); v3 = fmaf(x3.y, wb, v3); v3 = fmaf(x3.z, wc, v3); v3 = fmaf(x3.w, wd, v3);
                }
                #pragma unroll
                for (int j = 24; j < IN_DIR; j++) {
                    float wa = sWv[(HID + j) * 32 + lane];
                    v0 = fmaf(xdw[0 * 32 + j], wa, v0);
                    v1 = fmaf(xdw[1 * 32 + j], wa, v1);
                    v2 = fmaf(xdw[2 * 32 + j], wa, v2);
                    v3 = fmaf(xdw[3 * 32 + j], wa, v3);
                }
                v0 = fmaxf(v0, 0.f); v1 = fmaxf(v1, 0.f); v2 = fmaxf(v2, 0.f); v3 = fmaxf(v3, 0.f);

                float r0x = v0 * wr0, r0y = v0 * wr1, r0z = v0 * wr2;
                float r1x = v1 * wr0, r1y = v1 * wr1, r1z = v1 * wr2;
                float r2x = v2 * wr0, r2y = v2 * wr1, r2z = v2 * wr2;
                float r3x = v3 * wr0, r3y = v3 * wr1, r3z = v3 * wr2;

                #pragma unroll
                for (int o = 16; o > 0; o >>= 1) {
                    s0  += __shfl_xor_sync(0xFFFFFFFFu, s0,  o);
                    s1  += __shfl_xor_sync(0xFFFFFFFFu, s1,  o);
                    s2  += __shfl_xor_sync(0xFFFFFFFFu, s2,  o);
                    s3  += __shfl_xor_sync(0xFFFFFFFFu, s3,  o);
                    r0x += __shfl_xor_sync(0xFFFFFFFFu, r0x, o);
                    r0y += __shfl_xor_sync(0xFFFFFFFFu, r0y, o);
                    r0z += __shfl_xor_sync(0xFFFFFFFFu, r0z, o);
                    r1x += __shfl_xor_sync(0xFFFFFFFFu, r1x, o);
                    r1y += __shfl_xor_sync(0xFFFFFFFFu, r1y, o);
                    r1z += __shfl_xor_sync(0xFFFFFFFFu, r1z, o);
                    r2x += __shfl_xor_sync(0xFFFFFFFFu, r2x, o);
                    r2y += __shfl_xor_sync(0xFFFFFFFFu, r2y, o);
                    r2z += __shfl_xor_sync(0xFFFFFFFFu, r2z, o);
                    r3x += __shfl_xor_sync(0xFFFFFFFFu, r3x, o);
                    r3y += __shfl_xor_sync(0xFFFFFFFFu, r3y, o);
                    r3z += __shfl_xor_sync(0xFFFFFFFFu, r3z, o);
                }

                if (lane < 4 && kb + lane < count) {
                    int nn  = (lane == 0) ? n0  : (lane == 1) ? n1  : (lane == 2) ? n2  : n3;
                    float sv = (lane == 0) ? s0  : (lane == 1) ? s1  : (lane == 2) ? s2  : s3;
                    float cx = (lane == 0) ? r0x : (lane == 1) ? r1x : (lane == 2) ? r2x : r3x;
                    float cy = (lane == 0) ? r0y : (lane == 1) ? r1y : (lane == 2) ? r2y : r3y;
                    float cz = (lane == 0) ? r0z : (lane == 1) ? r1z : (lane == 2) ? r2z : r3z;
                    out_sig[nn] = sv + bsg;
                    out_rgb[(size_t)nn * 3 + 0] = cx + br0;
                    out_rgb[(size_t)nn * 3 + 1] = cy + br1;
                    out_rgb[(size_t)nn * 3 + 2] = cz + br2;
                }
                __syncwarp();
            }
        }
        __syncthreads();
        parity ^= 1;
        e_cur = e_next;
    }
}

// ---------------------------------------------------------------- launch
extern "C" void kernel_launch(void* const* d_in, const int* in_sizes, int n_in,
                              void* d_out, int out_size) {
    const float* pts  = (const float*)d_in[0];
    const float* dirs = (const float*)d_in[1];
    const float* W1   = (const float*)d_in[2];
    const float* b1   = (const float*)d_in[3];
    const float* W2   = (const float*)d_in[4];
    const float* b2   = (const float*)d_in[5];
    const float* Wf   = (const float*)d_in[6];
    const float* bf   = (const float*)d_in[7];
    const float* Wsig = (const float*)d_in[8];
    const float* bsig = (const float*)d_in[9];
    const float* Wv   = (const float*)d_in[10];
    const float* bv   = (const float*)d_in[11];
    const float* Wrgb = (const float*)d_in[12];
    const float* brgb = (const float*)d_in[13];

    float* out_rgb = (float*)d_out;
    float* out_sig = (float*)d_out + (size_t)NPTS * 3;

    cudaFuncSetAttribute(k_mlp, cudaFuncAttributeMaxDynamicSharedMemorySize, SMEM_BYTES);

    k_init<<<NEXP / 256, 256>>>(dirs);
    k_prep<<<NPTS / 256, 256>>>(pts);
    k_scan_scatter<<<257, 256>>>();
    k_mlp<<<GRID_MLP, 256, SMEM_BYTES>>>(W1, b1, W2, b2, Wf, bf, Wsig, bsig,
                                         Wv, bv, Wrgb, brgb, out_rgb, out_sig);
}